// round 3
// baseline (speedup 1.0000x reference)
#include <cuda_runtime.h>
#include <cstdint>

// Problem constants
#define BATCH   16
#define TLEN    4096
#define KW      15
#define PAD     7

// Tiling
#define TT      512     // time tile per CTA
#define TTH     16      // t positions per thread (8 packed adjacent pairs)
#define NTHREADS 256    // 8 oc * 32 t-subtiles
#define XP      (TT/2 + 8)   // padded pair-row length (needs TT/2+7)

typedef unsigned long long u64;

// ---------------------------------------------------------------------------
// Intermediate activation buffers (static device globals; no runtime alloc)
// ---------------------------------------------------------------------------
__device__ float g_h1[(size_t)BATCH * 512 * TLEN];  // leaf out   128 MiB
__device__ float g_h2[(size_t)BATCH * 256 * TLEN];  // int0 out    64 MiB
__device__ float g_h3[(size_t)BATCH * 256 * TLEN];  // br out      64 MiB
__device__ float g_h4[(size_t)BATCH * 128 * TLEN];  // int1 out    32 MiB
__device__ float g_h5[(size_t)BATCH *  64 * TLEN];  // int2 out    16 MiB
__device__ float g_h6[(size_t)BATCH *  32 * TLEN];  // int3 out     8 MiB
__device__ float g_h7[(size_t)BATCH *  16 * TLEN];  // int4 out     4 MiB

// ---------------------------------------------------------------------------
// Packed f32x2 helpers (FFMA2 only reachable via PTX)
// ---------------------------------------------------------------------------
__device__ __forceinline__ u64 pack2(float lo, float hi) {
    u64 r; asm("mov.b64 %0,{%1,%2};" : "=l"(r) : "f"(lo), "f"(hi)); return r;
}
__device__ __forceinline__ void unpack2(u64 v, float& lo, float& hi) {
    asm("mov.b64 {%0,%1},%2;" : "=f"(lo), "=f"(hi) : "l"(v));
}
__device__ __forceinline__ u64 ffma2(u64 a, u64 b, u64 c) {
    u64 d; asm("fma.rn.f32x2 %0,%1,%2,%3;" : "=l"(d) : "l"(a), "l"(b), "l"(c));
    return d;
}

// ---------------------------------------------------------------------------
// Grouped conv1d, K=15, SAME padding.
// Input staged in shared in TWO pre-packed f32x2 alignments:
//   E[ci][i] = (X[2i],   X[2i+1])      (even-tap operand)
//   O[ci][i] = (X[2i+1], X[2i+2])      (odd-tap operand)
// where X[tl] = x[t0 + tl - 7].  Tap k, acc pair a (outputs base+2a, base+2a+1):
//   k even: acc[a] += w2[k] * E[base/2 + a + (k>>1)]
//   k odd : acc[a] += w2[k] * O[base/2 + a + (k>>1)]
// -> the hot loop is ONLY LDS.64 + FFMA2, no register repacking.
//
// Grid: (TLEN/TT, groups, BATCH). Block: 256 = 8 oc * 32 t-subtiles.
// Dyn smem: [ sw2: COUT*(CIN*KW+1) u64 | E: CIN*XP u64 | O: CIN*XP u64 | sb ]
// ---------------------------------------------------------------------------
template<int CIN, int C0, int COUT, bool ACT>
__global__ __launch_bounds__(NTHREADS)
void gconv_kernel(const float* __restrict__ in0, long long bs0,
                  const float* __restrict__ in1, long long bs1,
                  const float* __restrict__ W,
                  const float* __restrict__ bias,
                  float* __restrict__ out, int G)
{
    extern __shared__ char smem_raw[];
    const int WROW = CIN * KW + 1;          // odd u64 stride: oc rows on distinct banks
    u64*   sw2 = (u64*)smem_raw;
    u64*   sE  = sw2 + COUT * WROW;
    u64*   sO  = sE + CIN * XP;
    float* sb  = (float*)(sO + CIN * XP);

    const int b   = blockIdx.z;
    const int g   = blockIdx.y;
    const int t0  = blockIdx.x * TT;
    const int tid = threadIdx.x;

    // ---- stage packed (w,w) weights for this group ----
    {
        const float* wsrc = W + (long long)g * COUT * CIN * KW;
        for (int i = tid; i < COUT * CIN * KW; i += NTHREADS) {
            int oc = i / (CIN * KW);
            int r  = i - oc * (CIN * KW);
            float w = wsrc[i];
            sw2[oc * WROW + r] = pack2(w, w);
        }
        if (tid < COUT) sb[tid] = bias[g * COUT + tid];
    }

    // ---- stage input pairs in both alignments ----
    for (int idx = tid; idx < CIN * XP; idx += NTHREADS) {
        int ci = idx / XP;
        int i  = idx - ci * XP;
        const float* src;
        if (C0 == CIN || ci < C0)
            src = in0 + (long long)b * bs0 + (long long)(g * C0 + ci) * TLEN;
        else
            src = in1 + (long long)b * bs1 + (long long)(g * (CIN - C0) + (ci - C0)) * TLEN;
        int tA = t0 + 2 * i - PAD;          // X[2i]
        float v0 = (tA     >= 0 && tA     < TLEN) ? src[tA]     : 0.0f;
        float v1 = (tA + 1 >= 0 && tA + 1 < TLEN) ? src[tA + 1] : 0.0f;
        float v2 = (tA + 2 >= 0 && tA + 2 < TLEN) ? src[tA + 2] : 0.0f;
        sE[idx] = pack2(v0, v1);
        sO[idx] = pack2(v1, v2);
    }
    __syncthreads();

    // ---- compute ----
    const int oc    = tid & (COUT - 1);     // oc lane-minor (weight rows spread banks)
    const int tt    = tid >> 3;             // 0..31
    const int basep = tt * (TTH / 2);       // pair index of first output pair

    u64 acc[8];
#pragma unroll
    for (int j = 0; j < 8; j++) acc[j] = 0ull;

    const u64* wrow = sw2 + oc * WROW;

#pragma unroll 1
    for (int ci = 0; ci < CIN; ci++) {
        const u64* ep = sE + ci * XP + basep;
        const u64* op = sO + ci * XP + basep;
        // register windows: e[0..14], o[0..13]
        u64 e[15], o[14];
#pragma unroll
        for (int i = 0; i < 15; i++) e[i] = ep[i];
#pragma unroll
        for (int i = 0; i < 14; i++) o[i] = op[i];

        const u64* wp = wrow + ci * KW;
#pragma unroll
        for (int k = 0; k < KW; k++) {
            u64 w2 = wp[k];
            int m = k >> 1;
            if ((k & 1) == 0) {
#pragma unroll
                for (int a = 0; a < 8; a++) acc[a] = ffma2(e[a + m], w2, acc[a]);
            } else {
#pragma unroll
                for (int a = 0; a < 8; a++) acc[a] = ffma2(o[a + m], w2, acc[a]);
            }
        }
    }

    // ---- epilogue: bias + leaky relu, vectorized store ----
    const float bv = sb[oc];
    float res[TTH];
#pragma unroll
    for (int j = 0; j < 8; j++) {
        float lo, hi;
        unpack2(acc[j], lo, hi);
        lo += bv; hi += bv;
        if (ACT) { lo = lo > 0.0f ? lo : 0.01f * lo; hi = hi > 0.0f ? hi : 0.01f * hi; }
        res[2 * j] = lo; res[2 * j + 1] = hi;
    }
    float* dst = out + (((long long)b * G + g) * COUT + oc) * TLEN + t0 + tt * TTH;
#pragma unroll
    for (int j = 0; j < 4; j++)
        ((float4*)dst)[j] = make_float4(res[4*j], res[4*j+1], res[4*j+2], res[4*j+3]);
}

// ---------------------------------------------------------------------------
// Root: 1x1 conv over 16 channels -> 1 channel (no activation)
// ---------------------------------------------------------------------------
__global__ void root_kernel(const float* __restrict__ h,
                            const float* __restrict__ w,
                            const float* __restrict__ bias,
                            float* __restrict__ out)
{
    int idx = blockIdx.x * blockDim.x + threadIdx.x;   // over BATCH*TLEN
    if (idx >= BATCH * TLEN) return;
    int b = idx / TLEN;
    int t = idx - b * TLEN;
    const float* hp = h + (long long)b * 16 * TLEN + t;
    float s = bias[0];
#pragma unroll
    for (int c = 0; c < 16; c++)
        s = fmaf(__ldg(&w[c]), hp[(long long)c * TLEN], s);
    out[idx] = s;
}

// ---------------------------------------------------------------------------
// Launch
// ---------------------------------------------------------------------------
static inline int smem_bytes(int cin, int cout) {
    return cout * (cin * KW + 1) * 8      // packed weights
         + cin * XP * 8 * 2               // E + O
         + cout * 4;                      // bias
}

extern "C" void kernel_launch(void* const* d_in, const int* in_sizes, int n_in,
                              void* d_out, int out_size)
{
    const float* x      = (const float*)d_in[0];
    const float* W_leaf = (const float*)d_in[1];
    const float* b_leaf = (const float*)d_in[2];
    const float* W_int0 = (const float*)d_in[3];
    const float* b_int0 = (const float*)d_in[4];
    const float* W_br   = (const float*)d_in[5];
    const float* b_br   = (const float*)d_in[6];
    const float* W_int1 = (const float*)d_in[7];
    const float* b_int1 = (const float*)d_in[8];
    const float* W_int2 = (const float*)d_in[9];
    const float* b_int2 = (const float*)d_in[10];
    const float* W_int3 = (const float*)d_in[11];
    const float* b_int3 = (const float*)d_in[12];
    const float* W_int4 = (const float*)d_in[13];
    const float* b_int4 = (const float*)d_in[14];
    const float* W_root = (const float*)d_in[15];
    const float* b_root = (const float*)d_in[16];
    float* out = (float*)d_out;

    float *h1, *h2, *h3, *h4, *h5, *h6, *h7;
    cudaGetSymbolAddress((void**)&h1, g_h1);
    cudaGetSymbolAddress((void**)&h2, g_h2);
    cudaGetSymbolAddress((void**)&h3, g_h3);
    cudaGetSymbolAddress((void**)&h4, g_h4);
    cudaGetSymbolAddress((void**)&h5, g_h5);
    cudaGetSymbolAddress((void**)&h6, g_h6);
    cudaGetSymbolAddress((void**)&h7, g_h7);

    const int TB = TLEN / TT;   // 8 tiles along T
    const long long BSX = (long long)1536 * TLEN;

    const int SM20 = smem_bytes(20, 8);
    const int SM16 = smem_bytes(16, 8);

    cudaFuncSetAttribute(gconv_kernel<20, 20, 8, true>,
                         cudaFuncAttributeMaxDynamicSharedMemorySize, SM20);
    cudaFuncSetAttribute(gconv_kernel<16, 16, 8, true>,
                         cudaFuncAttributeMaxDynamicSharedMemorySize, SM16);
    cudaFuncSetAttribute(gconv_kernel<16, 8, 8, true>,
                         cudaFuncAttributeMaxDynamicSharedMemorySize, SM16);

    // 1. leaf: 64 groups, 20 in/group, 8 out/group
    gconv_kernel<20, 20, 8, true><<<dim3(TB, 64, BATCH), NTHREADS, SM20>>>(
        x, BSX, nullptr, 0, W_leaf, b_leaf, h1, 64);

    // 2. int0: 32 groups, 16 in/group (from 512 ch)
    gconv_kernel<16, 16, 8, true><<<dim3(TB, 32, BATCH), NTHREADS, SM16>>>(
        h1, (long long)512 * TLEN, nullptr, 0, W_int0, b_int0, h2, 32);

    // 3. br: 32 groups, in/group = 8 (h2) + 8 (syn = x channels 1280..1535)
    gconv_kernel<16, 8, 8, true><<<dim3(TB, 32, BATCH), NTHREADS, SM16>>>(
        h2, (long long)256 * TLEN,
        x + (long long)1280 * TLEN, BSX,
        W_br, b_br, h3, 32);

    // 4. int1: 16 groups (256 -> 128)
    gconv_kernel<16, 16, 8, true><<<dim3(TB, 16, BATCH), NTHREADS, SM16>>>(
        h3, (long long)256 * TLEN, nullptr, 0, W_int1, b_int1, h4, 16);

    // 5. int2: 8 groups (128 -> 64)
    gconv_kernel<16, 16, 8, true><<<dim3(TB, 8, BATCH), NTHREADS, SM16>>>(
        h4, (long long)128 * TLEN, nullptr, 0, W_int2, b_int2, h5, 8);

    // 6. int3: 4 groups (64 -> 32)
    gconv_kernel<16, 16, 8, true><<<dim3(TB, 4, BATCH), NTHREADS, SM16>>>(
        h5, (long long)64 * TLEN, nullptr, 0, W_int3, b_int3, h6, 4);

    // 7. int4: 2 groups (32 -> 16)
    gconv_kernel<16, 16, 8, true><<<dim3(TB, 2, BATCH), NTHREADS, SM16>>>(
        h6, (long long)32 * TLEN, nullptr, 0, W_int4, b_int4, h7, 2);

    // 8. root: 1x1 conv 16 -> 1
    root_kernel<<<(BATCH * TLEN + 255) / 256, 256>>>(h7, W_root, b_root, out);
}

// round 4
// speedup vs baseline: 1.1428x; 1.1428x over previous
#include <cuda_runtime.h>
#include <cstdint>

// Problem constants
#define BATCH   16
#define TLEN    4096
#define KW      15
#define PAD     7

// Tiling
#define TT      512     // time tile per CTA
#define TTH     16      // t positions per thread (8 packed adjacent pairs)
#define NTHREADS 256    // 8 oc * 32 t-subtiles
#define XP      (TT/2 + 8)   // padded pair-row length (needs TT/2+7)

typedef unsigned long long u64;

// ---------------------------------------------------------------------------
// Intermediate activation buffers (static device globals; no runtime alloc)
// ---------------------------------------------------------------------------
__device__ float g_h1[(size_t)BATCH * 512 * TLEN];  // leaf out   128 MiB
__device__ float g_h2[(size_t)BATCH * 256 * TLEN];  // int0 out    64 MiB
__device__ float g_h3[(size_t)BATCH * 256 * TLEN];  // br out      64 MiB
__device__ float g_h4[(size_t)BATCH * 128 * TLEN];  // int1 out    32 MiB
__device__ float g_h5[(size_t)BATCH *  64 * TLEN];  // int2 out    16 MiB
__device__ float g_h6[(size_t)BATCH *  32 * TLEN];  // int3 out     8 MiB
__device__ float g_h7[(size_t)BATCH *  16 * TLEN];  // int4 out     4 MiB

// ---------------------------------------------------------------------------
// Packed f32x2 helpers (FFMA2 only reachable via PTX)
// ---------------------------------------------------------------------------
__device__ __forceinline__ u64 pack2(float lo, float hi) {
    u64 r; asm("mov.b64 %0,{%1,%2};" : "=l"(r) : "f"(lo), "f"(hi)); return r;
}
__device__ __forceinline__ void unpack2(u64 v, float& lo, float& hi) {
    asm("mov.b64 {%0,%1},%2;" : "=f"(lo), "=f"(hi) : "l"(v));
}
__device__ __forceinline__ u64 ffma2(u64 a, u64 b, u64 c) {
    u64 d; asm("fma.rn.f32x2 %0,%1,%2,%3;" : "=l"(d) : "l"(a), "l"(b), "l"(c));
    return d;
}

// ---------------------------------------------------------------------------
// Grouped conv1d, K=15, SAME padding.
// Input staged in shared in TWO pre-packed f32x2 alignments, CHUNK channels
// at a time (keeps smem small -> 3 CTAs/SM -> 24 warps):
//   E[ci][i] = (X[2i],   X[2i+1])      (even-tap operand)
//   O[ci][i] = (X[2i+1], X[2i+2])      (odd-tap operand)
// X[tl] = x[t0 + tl - 7].  Tap k, acc pair a:
//   k even: acc[a] += w2[k] * E[basep + a + (k>>1)]
//   k odd : acc[a] += w2[k] * O[basep + a + (k>>1)]
// Hot loop is ONLY LDS.64 + FFMA2 (density ~0.73).
//
// Grid: (TLEN/TT, groups, BATCH). Block: 256 = 8 oc * 32 t-subtiles.
// Dyn smem: [ sw2: COUT*(CIN*KW+1) u64 | E: CHUNK*XP u64 | O: CHUNK*XP u64 | sb ]
// ---------------------------------------------------------------------------
template<int CIN, int C0, int COUT, int CHUNK, bool ACT>
__global__ __launch_bounds__(NTHREADS, 3)
void gconv_kernel(const float* __restrict__ in0, long long bs0,
                  const float* __restrict__ in1, long long bs1,
                  const float* __restrict__ W,
                  const float* __restrict__ bias,
                  float* __restrict__ out, int G)
{
    extern __shared__ char smem_raw[];
    const int WROW = CIN * KW + 1;          // odd u64 stride: oc rows spread banks
    u64*   sw2 = (u64*)smem_raw;
    u64*   sE  = sw2 + COUT * WROW;
    u64*   sO  = sE + CHUNK * XP;
    float* sb  = (float*)(sO + CHUNK * XP);

    const int b   = blockIdx.z;
    const int g   = blockIdx.y;
    const int t0  = blockIdx.x * TT;
    const int tid = threadIdx.x;

    // ---- stage packed (w,w) weights for this group (full CIN, once) ----
    {
        const float* wsrc = W + (long long)g * COUT * CIN * KW;
        for (int i = tid; i < COUT * CIN * KW; i += NTHREADS) {
            int oc = i / (CIN * KW);
            int r  = i - oc * (CIN * KW);
            float w = wsrc[i];
            sw2[oc * WROW + r] = pack2(w, w);
        }
        if (tid < COUT) sb[tid] = bias[g * COUT + tid];
    }

    const int oc    = tid & (COUT - 1);     // oc lane-minor
    const int tt    = tid >> 3;             // 0..31
    const int basep = tt * (TTH / 2);       // first output pair index

    u64 acc[8];
#pragma unroll
    for (int j = 0; j < 8; j++) acc[j] = 0ull;

    const u64* wrow = sw2 + oc * WROW;

    // ---- loop over channel chunks: stage -> compute ----
#pragma unroll 1
    for (int c0 = 0; c0 < CIN; c0 += CHUNK) {
        __syncthreads();   // protect prior compute (WAR) / weight staging (chunk 0)

        for (int idx = tid; idx < CHUNK * XP; idx += NTHREADS) {
            int cl = idx / XP;
            int i  = idx - cl * XP;
            int ci = c0 + cl;
            const float* src;
            if (C0 == CIN || ci < C0)
                src = in0 + (long long)b * bs0 + (long long)(g * C0 + ci) * TLEN;
            else
                src = in1 + (long long)b * bs1 + (long long)(g * (CIN - C0) + (ci - C0)) * TLEN;
            int tA = t0 + 2 * i - PAD;          // X[2i]
            float v0 = (tA     >= 0 && tA     < TLEN) ? src[tA]     : 0.0f;
            float v1 = (tA + 1 >= 0 && tA + 1 < TLEN) ? src[tA + 1] : 0.0f;
            float v2 = (tA + 2 >= 0 && tA + 2 < TLEN) ? src[tA + 2] : 0.0f;
            sE[idx] = pack2(v0, v1);
            sO[idx] = pack2(v1, v2);
        }
        __syncthreads();

#pragma unroll 1
        for (int cl = 0; cl < CHUNK; cl++) {
            const u64* ep = sE + cl * XP + basep;
            const u64* op = sO + cl * XP + basep;
            u64 e[15], o[14];
#pragma unroll
            for (int i = 0; i < 15; i++) e[i] = ep[i];
#pragma unroll
            for (int i = 0; i < 14; i++) o[i] = op[i];

            const u64* wp = wrow + (c0 + cl) * KW;
#pragma unroll
            for (int k = 0; k < KW; k++) {
                u64 w2 = wp[k];
                int m = k >> 1;
                if ((k & 1) == 0) {
#pragma unroll
                    for (int a = 0; a < 8; a++) acc[a] = ffma2(e[a + m], w2, acc[a]);
                } else {
#pragma unroll
                    for (int a = 0; a < 8; a++) acc[a] = ffma2(o[a + m], w2, acc[a]);
                }
            }
        }
    }

    // ---- epilogue: bias + leaky relu, vectorized store ----
    const float bv = sb[oc];
    float res[TTH];
#pragma unroll
    for (int j = 0; j < 8; j++) {
        float lo, hi;
        unpack2(acc[j], lo, hi);
        lo += bv; hi += bv;
        if (ACT) { lo = lo > 0.0f ? lo : 0.01f * lo; hi = hi > 0.0f ? hi : 0.01f * hi; }
        res[2 * j] = lo; res[2 * j + 1] = hi;
    }
    float* dst = out + (((long long)b * G + g) * COUT + oc) * TLEN + t0 + tt * TTH;
#pragma unroll
    for (int j = 0; j < 4; j++)
        ((float4*)dst)[j] = make_float4(res[4*j], res[4*j+1], res[4*j+2], res[4*j+3]);
}

// ---------------------------------------------------------------------------
// Root: 1x1 conv over 16 channels -> 1 channel (no activation)
// ---------------------------------------------------------------------------
__global__ void root_kernel(const float* __restrict__ h,
                            const float* __restrict__ w,
                            const float* __restrict__ bias,
                            float* __restrict__ out)
{
    int idx = blockIdx.x * blockDim.x + threadIdx.x;   // over BATCH*TLEN
    if (idx >= BATCH * TLEN) return;
    int b = idx / TLEN;
    int t = idx - b * TLEN;
    const float* hp = h + (long long)b * 16 * TLEN + t;
    float s = bias[0];
#pragma unroll
    for (int c = 0; c < 16; c++)
        s = fmaf(__ldg(&w[c]), hp[(long long)c * TLEN], s);
    out[idx] = s;
}

// ---------------------------------------------------------------------------
// Launch
// ---------------------------------------------------------------------------
static inline int smem_bytes(int cin, int cout, int chunk) {
    return cout * (cin * KW + 1) * 8      // packed weights
         + chunk * XP * 8 * 2             // E + O chunk
         + cout * 4;                      // bias
}

extern "C" void kernel_launch(void* const* d_in, const int* in_sizes, int n_in,
                              void* d_out, int out_size)
{
    const float* x      = (const float*)d_in[0];
    const float* W_leaf = (const float*)d_in[1];
    const float* b_leaf = (const float*)d_in[2];
    const float* W_int0 = (const float*)d_in[3];
    const float* b_int0 = (const float*)d_in[4];
    const float* W_br   = (const float*)d_in[5];
    const float* b_br   = (const float*)d_in[6];
    const float* W_int1 = (const float*)d_in[7];
    const float* b_int1 = (const float*)d_in[8];
    const float* W_int2 = (const float*)d_in[9];
    const float* b_int2 = (const float*)d_in[10];
    const float* W_int3 = (const float*)d_in[11];
    const float* b_int3 = (const float*)d_in[12];
    const float* W_int4 = (const float*)d_in[13];
    const float* b_int4 = (const float*)d_in[14];
    const float* W_root = (const float*)d_in[15];
    const float* b_root = (const float*)d_in[16];
    float* out = (float*)d_out;

    float *h1, *h2, *h3, *h4, *h5, *h6, *h7;
    cudaGetSymbolAddress((void**)&h1, g_h1);
    cudaGetSymbolAddress((void**)&h2, g_h2);
    cudaGetSymbolAddress((void**)&h3, g_h3);
    cudaGetSymbolAddress((void**)&h4, g_h4);
    cudaGetSymbolAddress((void**)&h5, g_h5);
    cudaGetSymbolAddress((void**)&h6, g_h6);
    cudaGetSymbolAddress((void**)&h7, g_h7);

    const int TB = TLEN / TT;   // 8 tiles along T
    const long long BSX = (long long)1536 * TLEN;

    const int SM20 = smem_bytes(20, 8, 5);
    const int SM16 = smem_bytes(16, 8, 8);

    cudaFuncSetAttribute(gconv_kernel<20, 20, 8, 5, true>,
                         cudaFuncAttributeMaxDynamicSharedMemorySize, SM20);
    cudaFuncSetAttribute(gconv_kernel<16, 16, 8, 8, true>,
                         cudaFuncAttributeMaxDynamicSharedMemorySize, SM16);
    cudaFuncSetAttribute(gconv_kernel<16, 8, 8, 8, true>,
                         cudaFuncAttributeMaxDynamicSharedMemorySize, SM16);

    // 1. leaf: 64 groups, 20 in/group, 8 out/group (chunks of 5)
    gconv_kernel<20, 20, 8, 5, true><<<dim3(TB, 64, BATCH), NTHREADS, SM20>>>(
        x, BSX, nullptr, 0, W_leaf, b_leaf, h1, 64);

    // 2. int0: 32 groups, 16 in/group (from 512 ch)
    gconv_kernel<16, 16, 8, 8, true><<<dim3(TB, 32, BATCH), NTHREADS, SM16>>>(
        h1, (long long)512 * TLEN, nullptr, 0, W_int0, b_int0, h2, 32);

    // 3. br: 32 groups, in/group = 8 (h2) + 8 (syn = x channels 1280..1535)
    gconv_kernel<16, 8, 8, 8, true><<<dim3(TB, 32, BATCH), NTHREADS, SM16>>>(
        h2, (long long)256 * TLEN,
        x + (long long)1280 * TLEN, BSX,
        W_br, b_br, h3, 32);

    // 4. int1: 16 groups (256 -> 128)
    gconv_kernel<16, 16, 8, 8, true><<<dim3(TB, 16, BATCH), NTHREADS, SM16>>>(
        h3, (long long)256 * TLEN, nullptr, 0, W_int1, b_int1, h4, 16);

    // 5. int2: 8 groups (128 -> 64)
    gconv_kernel<16, 16, 8, 8, true><<<dim3(TB, 8, BATCH), NTHREADS, SM16>>>(
        h4, (long long)128 * TLEN, nullptr, 0, W_int2, b_int2, h5, 8);

    // 6. int3: 4 groups (64 -> 32)
    gconv_kernel<16, 16, 8, 8, true><<<dim3(TB, 4, BATCH), NTHREADS, SM16>>>(
        h5, (long long)64 * TLEN, nullptr, 0, W_int3, b_int3, h6, 4);

    // 7. int4: 2 groups (32 -> 16)
    gconv_kernel<16, 16, 8, 8, true><<<dim3(TB, 2, BATCH), NTHREADS, SM16>>>(
        h6, (long long)32 * TLEN, nullptr, 0, W_int4, b_int4, h7, 2);

    // 8. root: 1x1 conv 16 -> 1
    root_kernel<<<(BATCH * TLEN + 255) / 256, 256>>>(h7, W_root, b_root, out);
}